// round 4
// baseline (speedup 1.0000x reference)
#include <cuda_runtime.h>

// Problem constants
#define NVEC   131072            // B*H*W = 32*64*64
#define CDIM   64
#define KCODES 512
#define PPB    128               // positions per block
#define NBLOCK (NVEC/PPB)        // 1024
#define NTHR   256
#define CHUNK  64                // codes per chunk
#define NCHUNK (KCODES/CHUNK)    // 8
#define TAU    0.03f             // rescue threshold (>> fp32 pipeline error)
#define RCAP   32768

// Output layout (flattened tuple, float32):
// [loss(1)] [quantized(32*64*64*64)] [encoding_indices(131072)] [perplexity(1)] [codes(131072)]
#define QUANT_ELEMS (32*64*64*64)
#define OUT_LOSS  0
#define OUT_QUANT 1
#define OUT_EIDX  (1 + QUANT_ELEMS)
#define OUT_PERP  (OUT_EIDX + NVEC)
#define OUT_CODES (OUT_PERP + 1)

// Device scratch (no allocations allowed)
__device__ float g_ET[CDIM*KCODES];   // transposed codebook: g_ET[c*512 + k]
__device__ float g_ee[KCODES];        // ||e_k||^2
__device__ float g_counts[KCODES];
__device__ float g_loss;
__device__ int   g_rescue_n;
__device__ int   g_rescue_pos[RCAP];
__device__ int   g_rescue_cand[RCAP]; // i1 | (i2<<16)

typedef unsigned long long u64;

__device__ __forceinline__ u64 dup2(float a){
    u64 r; asm("mov.b64 %0, {%1, %1};" : "=l"(r) : "f"(a)); return r;
}
__device__ __forceinline__ u64 pack2(float x, float y){
    u64 r; asm("mov.b64 %0, {%1, %2};" : "=l"(r) : "f"(x), "f"(y)); return r;
}
__device__ __forceinline__ u64 fma2(u64 a, u64 b, u64 c){
    u64 d; asm("fma.rn.f32x2 %0, %1, %2, %3;" : "=l"(d) : "l"(a), "l"(b), "l"(c)); return d;
}
__device__ __forceinline__ void unpack2(u64 a, float& x, float& y){
    asm("mov.b64 {%0, %1}, %2;" : "=f"(x), "=f"(y) : "l"(a));
}

// ---------------------------------------------------------------------------
// Prep: transpose E, compute ||e||^2, zero accumulators. grid=17 x 256 thr.
// ---------------------------------------------------------------------------
__global__ void vq_prep(const float* __restrict__ emb){
    int blk = blockIdx.x;
    if (blk < 16){
        for (int i = blk*2048 + threadIdx.x; i < (blk+1)*2048; i += NTHR){
            int k = i >> 6, c = i & 63;
            g_ET[c*KCODES + k] = emb[i];
        }
    } else {
        int t = threadIdx.x;
        for (int k = t; k < KCODES; k += NTHR){
            const float4* e4 = (const float4*)(emb + k*CDIM);
            float s = 0.f;
            #pragma unroll
            for (int q = 0; q < 16; q++){
                float4 v = e4[q];
                s = fmaf(v.x, v.x, s); s = fmaf(v.y, v.y, s);
                s = fmaf(v.z, v.z, s); s = fmaf(v.w, v.w, s);
            }
            g_ee[k] = s;
        }
        for (int k = t; k < KCODES; k += NTHR) g_counts[k] = 0.f;
        if (t == 0){ g_loss = 0.f; g_rescue_n = 0; }
    }
}

// ---------------------------------------------------------------------------
// Main kernel: distances + top-2 argmin + provisional outputs.
// ---------------------------------------------------------------------------
__global__ void __launch_bounds__(NTHR) vq_main(const float* __restrict__ x,
                                                const float* __restrict__ emb,
                                                float* __restrict__ out){
    extern __shared__ float sm[];
    float* xs   = sm;                   // [64][128]
    float* es   = xs + CDIM*PPB;        // [64][64]
    float* ees  = es + CDIM*CHUNK;      // [512]
    float* xxs  = ees + KCODES;         // [128]
    int*   idxs = (int*)(xxs + PPB);    // [128]
    float* lsum = (float*)(idxs + PPB); // [1]

    const int tid = threadIdx.x;
    const int tx = tid & 15;            // code group
    const int ty = tid >> 4;            // position group
    const int pos0 = blockIdx.x * PPB;
    const int b  = pos0 >> 12;
    const int s0 = pos0 & 4095;
    const float* xrow = x + (size_t)b*262144 + s0;

    #pragma unroll
    for (int i4 = tid; i4 < CDIM*PPB/4; i4 += NTHR){
        int c = i4 >> 5, j4 = i4 & 31;
        ((float4*)xs)[i4] = *(const float4*)(xrow + c*4096 + j4*4);
    }
    for (int i = tid; i < KCODES; i += NTHR) ees[i] = g_ee[i];
    if (tid == 0) *lsum = 0.f;
    __syncthreads();

    if (tid < PPB){
        float s = 0.f;
        #pragma unroll 16
        for (int k = 0; k < CDIM; k++){ float v = xs[k*PPB + tid]; s = fmaf(v, v, s); }
        xxs[tid] = s;
    }

    float bv1[8], bv2[8]; int bi1[8], bi2[8];
    #pragma unroll
    for (int u = 0; u < 8; u++){ bv1[u] = 3.4e38f; bi1[u] = 0; bv2[u] = 3.4e38f; bi2[u] = 0; }

    for (int ch = 0; ch < NCHUNK; ch++){
        for (int i4 = tid; i4 < CDIM*CHUNK/4; i4 += NTHR){
            int c = i4 >> 4, q = i4 & 15;
            ((float4*)es)[i4] = *(const float4*)(g_ET + c*KCODES + ch*CHUNK + q*4);
        }
        __syncthreads();

        u64 acc[8][2];
        #pragma unroll
        for (int u = 0; u < 8; u++){ acc[u][0] = 0ull; acc[u][1] = 0ull; }

        #pragma unroll 8
        for (int k = 0; k < CDIM; k++){
            float4 xa = *(const float4*)&xs[k*PPB + ty*8];
            float4 xb = *(const float4*)&xs[k*PPB + ty*8 + 4];
            float4 ev = *(const float4*)&es[k*CHUNK + tx*4];
            u64 e01 = pack2(ev.x, ev.y);
            u64 e23 = pack2(ev.z, ev.w);
            u64 xd;
            #define VQ_STEP(u, xv) xd = dup2(xv); \
                acc[u][0] = fma2(xd, e01, acc[u][0]); \
                acc[u][1] = fma2(xd, e23, acc[u][1]);
            VQ_STEP(0, xa.x) VQ_STEP(1, xa.y) VQ_STEP(2, xa.z) VQ_STEP(3, xa.w)
            VQ_STEP(4, xb.x) VQ_STEP(5, xb.y) VQ_STEP(6, xb.z) VQ_STEP(7, xb.w)
            #undef VQ_STEP
        }

        // Fold 4 codes into per-thread top-2. score = ||e||^2 - 2 x.e
        // Codes scanned in ascending order; strict < keeps first index (jnp tie rule).
        int cb = ch*CHUNK + tx*4;
        float e0 = ees[cb], e1 = ees[cb+1], e2 = ees[cb+2], e3 = ees[cb+3];
        #pragma unroll
        for (int u = 0; u < 8; u++){
            float d0, d1, d2, d3;
            unpack2(acc[u][0], d0, d1);
            unpack2(acc[u][1], d2, d3);
            float s;
            #define VQ_UPD(sv, id) \
                if (sv < bv1[u]){ bv2[u]=bv1[u]; bi2[u]=bi1[u]; bv1[u]=sv; bi1[u]=id; } \
                else if (sv < bv2[u]){ bv2[u]=sv; bi2[u]=id; }
            s = fmaf(-2.f, d0, e0); VQ_UPD(s, cb)
            s = fmaf(-2.f, d1, e1); VQ_UPD(s, cb+1)
            s = fmaf(-2.f, d2, e2); VQ_UPD(s, cb+2)
            s = fmaf(-2.f, d3, e3); VQ_UPD(s, cb+3)
            #undef VQ_UPD
        }
        __syncthreads();
    }

    // Cross-thread top-2 merge over the 16 tx lanes (bfly stays in half-warp)
    #pragma unroll
    for (int m = 1; m < 16; m <<= 1){
        #pragma unroll
        for (int u = 0; u < 8; u++){
            float ov1 = __shfl_xor_sync(0xffffffffu, bv1[u], m);
            int   oi1 = __shfl_xor_sync(0xffffffffu, bi1[u], m);
            float ov2 = __shfl_xor_sync(0xffffffffu, bv2[u], m);
            int   oi2 = __shfl_xor_sync(0xffffffffu, bi2[u], m);
            if (ov1 < bv1[u] || (ov1 == bv1[u] && oi1 < bi1[u])){
                // other's best wins; my best competes for second against other's second
                float nb2; int ni2;
                if (bv1[u] < ov2 || (bv1[u] == ov2 && bi1[u] < oi2)){ nb2 = bv1[u]; ni2 = bi1[u]; }
                else                                                 { nb2 = ov2;    ni2 = oi2;    }
                bv1[u] = ov1; bi1[u] = oi1; bv2[u] = nb2; bi2[u] = ni2;
            } else {
                if (ov1 < bv2[u] || (ov1 == bv2[u] && oi1 < bi2[u])){ bv2[u] = ov1; bi2[u] = oi1; }
            }
        }
    }

    if (tx == 0){
        float ml = 0.f;
        #pragma unroll
        for (int u = 0; u < 8; u++){
            int p = ty*8 + u;
            idxs[p] = bi1[u];
            ml += xxs[p] + bv1[u];
            atomicAdd(&g_counts[bi1[u]], 1.0f);
            if (bv2[u] - bv1[u] < TAU){
                int slot = atomicAdd(&g_rescue_n, 1);
                if (slot < RCAP){
                    g_rescue_pos[slot]  = pos0 + p;
                    g_rescue_cand[slot] = bi1[u] | (bi2[u] << 16);
                }
            }
        }
        atomicAdd(lsum, ml);
    }
    __syncthreads();
    if (tid == 0) atomicAdd(&g_loss, *lsum);

    if (tid < PPB){
        float fi = (float)idxs[tid];
        out[OUT_EIDX  + pos0 + tid] = fi;
        out[OUT_CODES + pos0 + tid] = fi;
    }

    float* q = out + OUT_QUANT + (size_t)b*262144 + s0;
    for (int i = tid; i < CDIM*PPB; i += NTHR){
        int c = i >> 7, j = i & 127;
        q[c*4096 + j] = emb[idxs[j]*CDIM + c];
    }
}

// ---------------------------------------------------------------------------
// Rescue: exact fp64 re-ranking of near-tied top-2 candidates; patch outputs.
// One warp per queue entry.
// ---------------------------------------------------------------------------
__global__ void vq_rescue(const float* __restrict__ x,
                          const float* __restrict__ emb,
                          float* __restrict__ out){
    int n = g_rescue_n; if (n > RCAP) n = RCAP;
    int lane  = threadIdx.x & 31;
    int warp  = (blockIdx.x * blockDim.x + threadIdx.x) >> 5;
    int nwarp = (gridDim.x * blockDim.x) >> 5;

    for (int e = warp; e < n; e += nwarp){
        int pos = g_rescue_pos[e];
        int pk  = g_rescue_cand[e];
        int i1 = pk & 0xffff, i2 = pk >> 16;
        int b = pos >> 12, s = pos & 4095;
        const float* xp = x + (size_t)b*262144 + s;

        double d1 = 0.0, d2 = 0.0;
        #pragma unroll
        for (int h = 0; h < 2; h++){
            int c = lane + h*32;
            double xv = (double)xp[(size_t)c*4096];
            double t1 = xv - (double)emb[i1*CDIM + c];
            double t2 = xv - (double)emb[i2*CDIM + c];
            d1 = fma(t1, t1, d1);
            d2 = fma(t2, t2, d2);
        }
        #pragma unroll
        for (int m = 16; m; m >>= 1){
            d1 += __shfl_xor_sync(0xffffffffu, d1, m);
            d2 += __shfl_xor_sync(0xffffffffu, d2, m);
        }

        // True ranking; exact tie -> lower index (jnp.argmin first-occurrence)
        int    lo  = (i1 < i2) ? i1 : i2;
        int    hi  = (i1 < i2) ? i2 : i1;
        double dlo = (i1 < i2) ? d1 : d2;
        double dhi = (i1 < i2) ? d2 : d1;
        int winner = (dhi < dlo) ? hi : lo;

        if (winner != i1){
            if (lane == 0){
                atomicAdd(&g_counts[i1], -1.0f);
                atomicAdd(&g_counts[winner], 1.0f);
                out[OUT_EIDX  + pos] = (float)winner;
                out[OUT_CODES + pos] = (float)winner;
            }
            float* q = out + OUT_QUANT + (size_t)b*262144 + s;
            #pragma unroll
            for (int h = 0; h < 2; h++){
                int c = lane + h*32;
                q[(size_t)c*4096] = emb[winner*CDIM + c];
            }
        }
    }
}

// ---------------------------------------------------------------------------
// Finalize: perplexity + loss scalars. 1 block x 512 threads.
// ---------------------------------------------------------------------------
__global__ void vq_finalize(float* __restrict__ out){
    __shared__ float red[KCODES];
    int t = threadIdx.x;
    float p = g_counts[t] * (1.0f / (float)NVEC);
    red[t] = p * logf(p + 1e-10f);
    __syncthreads();
    #pragma unroll
    for (int s2 = 256; s2 > 0; s2 >>= 1){
        if (t < s2) red[t] += red[t + s2];
        __syncthreads();
    }
    if (t == 0){
        out[OUT_PERP] = expf(-red[0]);
        out[OUT_LOSS] = 0.25f * g_loss * (1.0f / (float)QUANT_ELEMS);
    }
}

// ---------------------------------------------------------------------------
extern "C" void kernel_launch(void* const* d_in, const int* in_sizes, int n_in,
                              void* d_out, int out_size){
    const float* x   = (const float*)d_in[0];   // inputs (32,64,64,64) f32
    const float* emb = (const float*)d_in[1];   // emb_weight (512,64) f32
    float* out = (float*)d_out;

    const int smem_bytes = (CDIM*PPB + CDIM*CHUNK + KCODES + PPB)*4 + PPB*4 + 4;
    cudaFuncSetAttribute(vq_main, cudaFuncAttributeMaxDynamicSharedMemorySize, smem_bytes);

    vq_prep<<<17, NTHR>>>(emb);
    vq_main<<<NBLOCK, NTHR, smem_bytes>>>(x, emb, out);
    vq_rescue<<<64, 256>>>(x, emb, out);
    vq_finalize<<<1, KCODES>>>(out);
}